// round 1
// baseline (speedup 1.0000x reference)
#include <cuda_runtime.h>

// Problem constants (fixed by the dataset)
#define NTOK    65536
#define DDIM    256
#define KCODES  1024
#define MLVL    4
#define TM      128          // tokens per block
#define CK      64           // codebook chunk (codes) in SMEM
#define THREADS 256
#define RSTRIDE 132          // padded row stride (floats) for Rsh [d][token]
#define ESTRIDE 68           // padded row stride (floats) for Esh [d][code]
#define NBLOCKS (NTOK / TM)  // 512

__device__ float  g_e2[MLVL * KCODES];
__device__ double g_commitPartial[NBLOCKS];

static __device__ __forceinline__ unsigned long long pack2(float x, float y) {
    unsigned long long r;
    asm("mov.b64 %0, {%1, %2};" : "=l"(r) : "f"(x), "f"(y));
    return r;
}
static __device__ __forceinline__ void fma2(unsigned long long& d,
                                            unsigned long long a,
                                            unsigned long long b) {
    asm("fma.rn.f32x2 %0, %1, %2, %0;" : "+l"(d) : "l"(a), "l"(b));
}
static __device__ __forceinline__ float lo32(unsigned long long u) {
    return __uint_as_float((unsigned)(u & 0xffffffffull));
}
static __device__ __forceinline__ float hi32(unsigned long long u) {
    return __uint_as_float((unsigned)(u >> 32));
}

// ---------------------------------------------------------------------------
// e2[l][k] = sum_d cb[l][k][d]^2  (fp64 accumulate, rounded once to fp32,
// matching jnp.sum(cb*cb, axis=1) to within ~1 ulp)
// ---------------------------------------------------------------------------
__global__ void e2_kernel(const float* __restrict__ cb) {
    int warp = (blockIdx.x * blockDim.x + threadIdx.x) >> 5;
    int lane = threadIdx.x & 31;
    if (warp >= MLVL * KCODES) return;
    const float* row = cb + (size_t)warp * DDIM;
    double s = 0.0;
#pragma unroll
    for (int m = 0; m < DDIM / 32; m++) {
        float v = row[lane + 32 * m];
        s += (double)v * (double)v;
    }
#pragma unroll
    for (int off = 16; off; off >>= 1) s += __shfl_xor_sync(0xffffffffu, s, off);
    if (lane == 0) g_e2[warp] = (float)s;
}

// ---------------------------------------------------------------------------
// Main fused residual-VQ kernel: one block owns 128 tokens through all 4 levels.
// ---------------------------------------------------------------------------
__global__ __launch_bounds__(THREADS, 1)
void rvq_kernel(const float* __restrict__ X, const float* __restrict__ CB,
                float* __restrict__ Y) {
    extern __shared__ float smem[];
    float*  Rsh   = smem;                         // [DDIM][RSTRIDE] residual, d-major
    float*  Esh   = smem + DDIM * RSTRIDE;        // [DDIM][ESTRIDE] codebook chunk, d-major
    float*  r2Sh  = Esh + DDIM * ESTRIDE;         // [TM]
    int*    bestI = (int*)(r2Sh + TM);            // [TM]
    double* redD  = (double*)(bestI + TM);        // [THREADS]

    const int tid = threadIdx.x;
    const int tt  = tid >> 3;   // token-group thread (0..31)
    const int tc  = tid & 7;    // code-group thread  (0..7)
    const int t0  = tt * 4;     // 4 tokens per thread
    const long long tokenBase = (long long)blockIdx.x * TM;
    const float* Xblk = X + tokenBase * DDIM;

    // ---- load X tile transposed into Rsh -------------------------------
    for (int idx = tid; idx < TM * (DDIM / 4); idx += THREADS) {
        int t  = idx >> 6;
        int dq = (idx & 63) << 2;
        float4 v = *(const float4*)(Xblk + (long long)t * DDIM + dq);
        Rsh[(dq + 0) * RSTRIDE + t] = v.x;
        Rsh[(dq + 1) * RSTRIDE + t] = v.y;
        Rsh[(dq + 2) * RSTRIDE + t] = v.z;
        Rsh[(dq + 3) * RSTRIDE + t] = v.w;
    }
    __syncthreads();

    // ---- initial r2 per token (fp64 accumulate -> fp32 once) -----------
    {
        int t = tid >> 1, h = tid & 1;
        double s = 0.0;
        int base = h * 128;
        for (int k = 0; k < 128; k++) {
            float f = Rsh[(base + k) * RSTRIDE + t];
            s += (double)f * (double)f;
        }
        redD[tid] = s;
        __syncthreads();
        if (h == 0) r2Sh[t] = (float)(redD[tid] + redD[tid + 1]);
    }
    __syncthreads();

    double commitAcc = 0.0;

    for (int lvl = 0; lvl < MLVL; lvl++) {
        const float* cbL = CB + (size_t)lvl * KCODES * DDIM;
        const float* e2L = g_e2 + lvl * KCODES;

        float bv[4];
        int   bidx[4];
#pragma unroll
        for (int i = 0; i < 4; i++) { bv[i] = __int_as_float(0x7f800000); bidx[i] = 0; }

        for (int chunk = 0; chunk < KCODES / CK; chunk++) {
            __syncthreads();
            // ---- load codebook chunk transposed into Esh ----------------
            const float* cbC = cbL + (size_t)chunk * CK * DDIM;
            for (int idx = tid; idx < CK * (DDIM / 4); idx += THREADS) {
                int c  = idx >> 6;
                int dq = (idx & 63) << 2;
                float4 v = *(const float4*)(cbC + (long long)c * DDIM + dq);
                Esh[(dq + 0) * ESTRIDE + c] = v.x;
                Esh[(dq + 1) * ESTRIDE + c] = v.y;
                Esh[(dq + 2) * ESTRIDE + c] = v.z;
                Esh[(dq + 3) * ESTRIDE + c] = v.w;
            }
            __syncthreads();

            // ---- 4x8 register-tile GEMM with packed f32x2 FMA -----------
            unsigned long long acc[4][4];
#pragma unroll
            for (int i = 0; i < 4; i++)
#pragma unroll
                for (int j = 0; j < 4; j++) acc[i][j] = 0ull;

#pragma unroll 4
            for (int d = 0; d < DDIM; d++) {
                const float4 rv = *(const float4*)(Rsh + d * RSTRIDE + t0);
                const ulonglong2 ea = *(const ulonglong2*)(Esh + d * ESTRIDE + tc * 8);
                const ulonglong2 eb = *(const ulonglong2*)(Esh + d * ESTRIDE + tc * 8 + 4);
                unsigned long long a0 = pack2(rv.x, rv.x);
                unsigned long long a1 = pack2(rv.y, rv.y);
                unsigned long long a2 = pack2(rv.z, rv.z);
                unsigned long long a3 = pack2(rv.w, rv.w);
                fma2(acc[0][0], a0, ea.x); fma2(acc[0][1], a0, ea.y);
                fma2(acc[0][2], a0, eb.x); fma2(acc[0][3], a0, eb.y);
                fma2(acc[1][0], a1, ea.x); fma2(acc[1][1], a1, ea.y);
                fma2(acc[1][2], a1, eb.x); fma2(acc[1][3], a1, eb.y);
                fma2(acc[2][0], a2, ea.x); fma2(acc[2][1], a2, ea.y);
                fma2(acc[2][2], a2, eb.x); fma2(acc[2][3], a2, eb.y);
                fma2(acc[3][0], a3, ea.x); fma2(acc[3][1], a3, ea.y);
                fma2(acc[3][2], a3, eb.x); fma2(acc[3][3], a3, eb.y);
            }

            // ---- distances + running argmin (replicates reference fp32
            //      rounding: (r2 + e2) - 2*dot; ties -> lower index) ------
            const int cbase = chunk * CK + tc * 8;
            float e2v[8];
#pragma unroll
            for (int j = 0; j < 8; j++) e2v[j] = __ldg(&e2L[cbase + j]);
#pragma unroll
            for (int i = 0; i < 4; i++) {
                float r2t = r2Sh[t0 + i];
#pragma unroll
                for (int j = 0; j < 8; j++) {
                    unsigned long long u = acc[i][j >> 1];
                    float dot  = (j & 1) ? hi32(u) : lo32(u);
                    float dist = (r2t + e2v[j]) - 2.0f * dot;
                    if (dist < bv[i]) { bv[i] = dist; bidx[i] = cbase + j; }
                }
            }
        } // chunks

        // ---- cross-thread argmin over the 8 code-threads (same warp) ----
#pragma unroll
        for (int off = 1; off < 8; off <<= 1) {
#pragma unroll
            for (int i = 0; i < 4; i++) {
                float ov = __shfl_xor_sync(0xffffffffu, bv[i], off);
                int   oi = __shfl_xor_sync(0xffffffffu, bidx[i], off);
                if (ov < bv[i] || (ov == bv[i] && oi < bidx[i])) {
                    bv[i] = ov; bidx[i] = oi;
                }
            }
        }
        if (tc == 0) {
#pragma unroll
            for (int i = 0; i < 4; i++) bestI[t0 + i] = bidx[i];
        }
        __syncthreads();

        // ---- residual update, new r2, commit accumulation ---------------
        {
            int t = tid >> 1, h = tid & 1;
            int bi = bestI[t];
            const float* q = cbL + (size_t)bi * DDIM + h * 128;
            double ss = 0.0;
            for (int k = 0; k < 128; k += 4) {
                float4 qv = *(const float4*)(q + k);
                int r = (h * 128 + k) * RSTRIDE + t;
                float n0 = Rsh[r] - qv.x;                Rsh[r] = n0;
                float n1 = Rsh[r + RSTRIDE] - qv.y;      Rsh[r + RSTRIDE] = n1;
                float n2 = Rsh[r + 2 * RSTRIDE] - qv.z;  Rsh[r + 2 * RSTRIDE] = n2;
                float n3 = Rsh[r + 3 * RSTRIDE] - qv.w;  Rsh[r + 3 * RSTRIDE] = n3;
                ss += (double)n0 * n0 + (double)n1 * n1 +
                      (double)n2 * n2 + (double)n3 * n3;
            }
            redD[tid] = ss;
            commitAcc += ss;
            __syncthreads();
            if (h == 0) r2Sh[t] = (float)(redD[tid] + redD[tid + 1]);
        }
        __syncthreads();
    } // levels

    // ---- y = x - r_final (== q_sum up to the reference's own rounding) --
    for (int idx = tid; idx < TM * (DDIM / 4); idx += THREADS) {
        int t  = idx >> 6;
        int dq = (idx & 63) << 2;
        float4 xv = *(const float4*)(Xblk + (long long)t * DDIM + dq);
        float4 y;
        y.x = xv.x - Rsh[(dq + 0) * RSTRIDE + t];
        y.y = xv.y - Rsh[(dq + 1) * RSTRIDE + t];
        y.z = xv.z - Rsh[(dq + 2) * RSTRIDE + t];
        y.w = xv.w - Rsh[(dq + 3) * RSTRIDE + t];
        *(float4*)(Y + (tokenBase + t) * DDIM + dq) = y;
    }

    // ---- deterministic per-block commit partial -------------------------
    redD[tid] = commitAcc;
    for (int s = THREADS / 2; s > 0; s >>= 1) {
        __syncthreads();
        if (tid < s) redD[tid] += redD[tid + s];
    }
    if (tid == 0) g_commitPartial[blockIdx.x] = redD[0];
}

// ---------------------------------------------------------------------------
// Deterministic final reduction -> commit scalar appended after y
// ---------------------------------------------------------------------------
__global__ void finalize_kernel(float* __restrict__ Y, int out_size) {
    __shared__ double sd[NBLOCKS];
    int tid = threadIdx.x;
    sd[tid] = g_commitPartial[tid];
    for (int s = NBLOCKS / 2; s > 0; s >>= 1) {
        __syncthreads();
        if (tid < s) sd[tid] += sd[tid + s];
    }
    if (tid == 0) {
        double mean = sd[0] / (double)((long long)NTOK * DDIM);
        float commit = (float)(0.25 * mean);
        long long numel = (long long)NTOK * DDIM;
        for (long long j = numel; j < (long long)out_size; j++) Y[j] = commit;
    }
}

extern "C" void kernel_launch(void* const* d_in, const int* in_sizes, int n_in,
                              void* d_out, int out_size) {
    const float* X  = (const float*)d_in[0];
    const float* CB = (const float*)d_in[1];
    float* Y = (float*)d_out;

    size_t smem = (size_t)(DDIM * RSTRIDE + DDIM * ESTRIDE + TM) * sizeof(float)
                + (size_t)TM * sizeof(int)
                + (size_t)THREADS * sizeof(double);
    cudaFuncSetAttribute(rvq_kernel, cudaFuncAttributeMaxDynamicSharedMemorySize,
                         (int)smem);

    e2_kernel<<<(MLVL * KCODES * 32 + 255) / 256, 256>>>(CB);
    rvq_kernel<<<NBLOCKS, THREADS, smem>>>(X, CB, Y);
    finalize_kernel<<<1, NBLOCKS>>>(Y, out_size);
}

// round 4
// speedup vs baseline: 4.1278x; 4.1278x over previous
#include <cuda_runtime.h>
#include <cuda_bf16.h>
#include <cstdint>

// Problem constants
#define NTOK    65536
#define DDIM    256
#define KCODES  1024
#define MLVL    4
#define TM      128            // tokens per block
#define THREADS 256
#define RS      260            // fp32 residual row stride (floats)
#define NBLOCKS (NTOK / TM)    // 512
#define MARGIN  4e-4f

// SMEM byte offsets (dynamic smem, total 224776 <= 232448)
#define OFF_RSH    0
#define OFF_AFRAG  133120
#define OFF_BBUF   198656
// halfTop OVERLAYS the first 8KB of BBUF: only live between the end of the
// slice loop (both sl=63 barriers passed; only Bb[1] still read) and the
// rescue phase, strictly before the next level's prefetch into Bb[0].
#define OFF_HTD    198656              // float4 halfTopDist[2][128]  (4KB)
#define OFF_HTI    202752              // int4   halfTopIdx [2][128]  (4KB)
#define OFF_E2     215040
#define OFF_R2     219136
#define OFF_BEST   219648
#define OFF_CTOK   220160
#define OFF_CIDX   220672
#define OFF_CCNT   222720
#define OFF_REDD   222728
#define SMEM_TOTAL 224776

__device__ float  g_e2[MLVL * KCODES];
__device__ double g_commitPartial[NBLOCKS];
// B fragments: [lvl][slice(64)][512 x uint4]  (slice = nc*8 + kb, 8KB each)
__device__ uint4  g_cbfrag[MLVL * 64 * 512];

static __device__ __forceinline__ uint32_t pkbf(float a, float b) {
    __nv_bfloat162 h = __floats2bfloat162_rn(a, b);   // x=a (low), y=b (high)
    return *reinterpret_cast<uint32_t*>(&h);
}
static __device__ __forceinline__ void mma16816(float* c, const uint4& A,
                                                uint32_t b0, uint32_t b1) {
    asm volatile(
        "mma.sync.aligned.m16n8k16.row.col.f32.bf16.bf16.f32 "
        "{%0,%1,%2,%3}, {%4,%5,%6,%7}, {%8,%9}, {%0,%1,%2,%3};"
        : "+f"(c[0]), "+f"(c[1]), "+f"(c[2]), "+f"(c[3])
        : "r"(A.x), "r"(A.y), "r"(A.z), "r"(A.w), "r"(b0), "r"(b1));
}
static __device__ __forceinline__ void cpasync16(void* dst, const void* src) {
    uint32_t d = (uint32_t)__cvta_generic_to_shared(dst);
    asm volatile("cp.async.cg.shared.global [%0], [%1], 16;" :: "r"(d), "l"(src));
}
#define CP_COMMIT() asm volatile("cp.async.commit_group;")
#define CP_WAIT(n)  asm volatile("cp.async.wait_group %0;" :: "n"(n))

// ---------------------------------------------------------------------------
// e2[l][k] = sum_d cb^2 (fp64 accumulate -> fp32)
// ---------------------------------------------------------------------------
__global__ void e2_kernel(const float* __restrict__ cb) {
    int warp = (blockIdx.x * blockDim.x + threadIdx.x) >> 5;
    int lane = threadIdx.x & 31;
    if (warp >= MLVL * KCODES) return;
    const float* row = cb + (size_t)warp * DDIM;
    double s = 0.0;
#pragma unroll
    for (int m = 0; m < DDIM / 32; m++) {
        float v = row[lane + 32 * m];
        s += (double)v * (double)v;
    }
#pragma unroll
    for (int off = 16; off; off >>= 1) s += __shfl_xor_sync(0xffffffffu, s, off);
    if (lane == 0) g_e2[warp] = (float)s;
}

// ---------------------------------------------------------------------------
// Pre-pack codebooks as bf16 m16n8k16 B-fragments.
// n = nc*128 + half*64 + nt*8 + (lane>>2), k0 = kb*32 + (lane&3)*2
// uint4 = { (k0,k0+1), (k0+8,k0+9), (k0+16,k0+17), (k0+24,k0+25) }
// ---------------------------------------------------------------------------
__global__ void prep_cb(const float* __restrict__ cb) {
    int id = blockIdx.x * blockDim.x + threadIdx.x;
    if (id >= MLVL * 64 * 512) return;
    int s    = id >> 9;
    int u    = id & 511;
    int half = u >> 8;
    int nt   = (u >> 5) & 7;
    int lane = u & 31;
    int lvl  = s >> 6;
    int nc   = (s >> 3) & 7;
    int kb   = s & 7;
    int n  = nc * 128 + half * 64 + nt * 8 + (lane >> 2);
    int k0 = kb * 32 + (lane & 3) * 2;
    const float* row = cb + ((size_t)lvl * KCODES + n) * DDIM;
    uint4 v;
    v.x = pkbf(row[k0],      row[k0 + 1]);
    v.y = pkbf(row[k0 + 8],  row[k0 + 9]);
    v.z = pkbf(row[k0 + 16], row[k0 + 17]);
    v.w = pkbf(row[k0 + 24], row[k0 + 25]);
    g_cbfrag[id] = v;
}

// ---------------------------------------------------------------------------
// Streaming top-3 insert (strict <, stream order = ascending idx)
// ---------------------------------------------------------------------------
struct Top3 { float d0, d1, d2; int i0, i1, i2; };
static __device__ __forceinline__ void t3_insert(Top3& T, float d, int idx) {
    if (d < T.d2) {
        if (d < T.d1) {
            T.d2 = T.d1; T.i2 = T.i1;
            if (d < T.d0) { T.d1 = T.d0; T.i1 = T.i0; T.d0 = d; T.i0 = idx; }
            else          { T.d1 = d;    T.i1 = idx; }
        } else { T.d2 = d; T.i2 = idx; }
    }
}
// insert into sorted-4 with tie -> lower idx
static __device__ __forceinline__ void t4_insert(float* d, int* i, float nd, int ni) {
    bool l3 = (nd < d[3]) || (nd == d[3] && ni < i[3]);
    if (!l3) return;
    bool l2 = (nd < d[2]) || (nd == d[2] && ni < i[2]);
    bool l1 = (nd < d[1]) || (nd == d[1] && ni < i[1]);
    bool l0 = (nd < d[0]) || (nd == d[0] && ni < i[0]);
    if (l0)      { d[3]=d[2]; i[3]=i[2]; d[2]=d[1]; i[2]=i[1]; d[1]=d[0]; i[1]=i[0]; d[0]=nd; i[0]=ni; }
    else if (l1) { d[3]=d[2]; i[3]=i[2]; d[2]=d[1]; i[2]=i[1]; d[1]=nd; i[1]=ni; }
    else if (l2) { d[3]=d[2]; i[3]=i[2]; d[2]=nd; i[2]=ni; }
    else         { d[3]=nd; i[3]=ni; }
}

// ---------------------------------------------------------------------------
// Main fused residual-VQ kernel.
// ---------------------------------------------------------------------------
__global__ __launch_bounds__(THREADS, 1)
void rvq_mma(const float* __restrict__ X, const float* __restrict__ CB,
             float* __restrict__ Y) {
    extern __shared__ char smem[];
    float*  Rsh     = (float*)(smem + OFF_RSH);     // [128][260] fp32 residual
    uint4*  Af      = (uint4*)(smem + OFF_AFRAG);   // A fragments [mt8][ks16][lane32]
    uint4*  Bb      = (uint4*)(smem + OFF_BBUF);    // 2 x 512 uint4 (8KB slices)
    float4* htd     = (float4*)(smem + OFF_HTD);    // [2][128] per-half top-4 dists
    int4*   hti     = (int4*)(smem + OFF_HTI);      // [2][128] per-half top-4 idxs
    float*  e2Sh    = (float*)(smem + OFF_E2);      // [1024]
    float*  r2Sh    = (float*)(smem + OFF_R2);      // [128]
    int*    bestI   = (int*)(smem + OFF_BEST);      // [128]
    int*    candTok = (int*)(smem + OFF_CTOK);      // [128]
    int4*   candIdx = (int4*)(smem + OFF_CIDX);     // [128]
    int*    candCnt = (int*)(smem + OFF_CCNT);
    double* redD    = (double*)(smem + OFF_REDD);   // [256]

    const int tid  = threadIdx.x;
    const int wid  = tid >> 5;
    const int lane = tid & 31;
    const int wm   = wid & 3;    // M group: rows [wm*32, wm*32+32)
    const int wn   = wid >> 2;   // N half within each 128-code chunk
    const int g    = lane >> 2;  // groupID
    const int tg2  = (lane & 3) * 2;
    const long long tokenBase = (long long)blockIdx.x * TM;
    const float* Xblk = X + tokenBase * DDIM;
    const float INF = __int_as_float(0x7f800000);

    // ---- load X tile -----------------------------------------------------
    for (int idx = tid; idx < TM * (DDIM / 4); idx += THREADS) {
        int t = idx >> 6, dq = (idx & 63) << 2;
        *(float4*)(Rsh + t * RS + dq) = *(const float4*)(Xblk + (long long)t * DDIM + dq);
    }
    __syncthreads();

    // ---- initial r2 (fp64 -> fp32) ---------------------------------------
    {
        int t = tid >> 1, h = tid & 1;
        const float* rr = Rsh + t * RS + h * 128;
        double s = 0.0;
        for (int k = 0; k < 128; k++) { float f = rr[k]; s += (double)f * f; }
        redD[tid] = s;
        __syncthreads();
        if (!h) r2Sh[t] = (float)(redD[tid] + redD[tid + 1]);
    }
    __syncthreads();

    double commitAcc = 0.0;

    for (int lvl = 0; lvl < MLVL; lvl++) {
        // ---- level setup: e2, candCnt, A fragments (bf16) ----------------
        if (tid == 0) *candCnt = 0;
        for (int i = tid; i < KCODES; i += THREADS) e2Sh[i] = g_e2[lvl * KCODES + i];
        for (int idx = tid; idx < 8 * 16 * 32; idx += THREADS) {
            int mt = idx >> 9, ks = (idx >> 5) & 15, ln = idx & 31;
            int m0 = mt * 16 + (ln >> 2);
            int k0 = ks * 16 + (ln & 3) * 2;
            const float* ra = Rsh + m0 * RS;
            const float* rb = Rsh + (m0 + 8) * RS;
            uint4 v;
            v.x = pkbf(ra[k0],     ra[k0 + 1]);
            v.y = pkbf(rb[k0],     rb[k0 + 1]);
            v.z = pkbf(ra[k0 + 8], ra[k0 + 9]);
            v.w = pkbf(rb[k0 + 8], rb[k0 + 9]);
            Af[idx] = v;
        }
        __syncthreads();

        // per-warp hoisted r2 values: [mt][rowhalf]
        float r2v[2][2];
#pragma unroll
        for (int mt = 0; mt < 2; mt++) {
            int tk = (wm * 2 + mt) * 16 + g;
            r2v[mt][0] = r2Sh[tk];
            r2v[mt][1] = r2Sh[tk + 8];
        }

        // top-3 structs: [mt*2 + rowhalf]
        Top3 T[4];
#pragma unroll
        for (int q = 0; q < 4; q++) { T[q].d0 = T[q].d1 = T[q].d2 = INF; T[q].i0 = T[q].i1 = T[q].i2 = 0x7fffffff; }

        const uint4* gb = g_cbfrag + (size_t)lvl * 64 * 512;
        float acc[2][8][4];

        // prefetch slice 0
        cpasync16(Bb + tid * 2,     gb + tid * 2);
        cpasync16(Bb + tid * 2 + 1, gb + tid * 2 + 1);
        CP_COMMIT();

        for (int sl = 0; sl < 64; sl++) {
            const int cur = sl & 1;
            const int kb  = sl & 7;
            __syncthreads();   // everyone done with buf[1-cur] (prev compute)
            if (sl + 1 < 64) {
                const uint4* src = gb + (size_t)(sl + 1) * 512 + tid * 2;
                uint4* dst = Bb + (1 - cur) * 512 + tid * 2;
                cpasync16(dst, src);
                cpasync16(dst + 1, src + 1);
                CP_COMMIT();
                CP_WAIT(1);
            } else {
                CP_WAIT(0);
            }
            __syncthreads();   // slice 'cur' visible to all

            if (kb == 0) {
#pragma unroll
                for (int mt = 0; mt < 2; mt++)
#pragma unroll
                    for (int nt = 0; nt < 8; nt++)
#pragma unroll
                        for (int c = 0; c < 4; c++) acc[mt][nt][c] = 0.f;
            }

            // A fragments for this k-block (2 mtiles x 2 ksteps)
            uint4 A00 = Af[(((wm * 2 + 0) * 16) + kb * 2 + 0) * 32 + lane];
            uint4 A01 = Af[(((wm * 2 + 0) * 16) + kb * 2 + 1) * 32 + lane];
            uint4 A10 = Af[(((wm * 2 + 1) * 16) + kb * 2 + 0) * 32 + lane];
            uint4 A11 = Af[(((wm * 2 + 1) * 16) + kb * 2 + 1) * 32 + lane];
            const uint4* Bp = Bb + cur * 512 + wn * 256 + lane;
#pragma unroll
            for (int nt = 0; nt < 8; nt++) {
                uint4 Bv = Bp[nt * 32];
                mma16816(acc[0][nt], A00, Bv.x, Bv.y);
                mma16816(acc[1][nt], A10, Bv.x, Bv.y);
                mma16816(acc[0][nt], A01, Bv.z, Bv.w);
                mma16816(acc[1][nt], A11, Bv.z, Bv.w);
            }

            // ---- per-chunk epilogue: dist + top-3 streaming --------------
            if (kb == 7) {
                const int nc = sl >> 3;
#pragma unroll
                for (int mt = 0; mt < 2; mt++) {
#pragma unroll
                    for (int nt = 0; nt < 8; nt++) {
                        int nbase = nc * 128 + wn * 64 + nt * 8 + tg2;
                        float2 e2p = *(const float2*)&e2Sh[nbase];
                        float s00 = r2v[mt][0] + e2p.x;
                        float s01 = r2v[mt][0] + e2p.y;
                        float s10 = r2v[mt][1] + e2p.x;
                        float s11 = r2v[mt][1] + e2p.y;
                        t3_insert(T[mt * 2 + 0], fmaf(-2.f, acc[mt][nt][0], s00), nbase);
                        t3_insert(T[mt * 2 + 0], fmaf(-2.f, acc[mt][nt][1], s01), nbase + 1);
                        t3_insert(T[mt * 2 + 1], fmaf(-2.f, acc[mt][nt][2], s10), nbase);
                        t3_insert(T[mt * 2 + 1], fmaf(-2.f, acc[mt][nt][3], s11), nbase + 1);
                    }
                }
            }
        } // slices

        // ---- quad merge, then publish per-(wn,token) top-4 to SMEM -------
        // (lanes lane&3 = 0..3 hold disjoint code subsets of this warp's half)
#pragma unroll
        for (int q = 0; q < 4; q++) {
            float md[4] = { T[q].d0, T[q].d1, T[q].d2, INF };
            int   mi[4] = { T[q].i0, T[q].i1, T[q].i2, 0x7fffffff };
#pragma unroll
            for (int off = 1; off <= 2; off <<= 1) {
                float od[4]; int oi[4];
#pragma unroll
                for (int j = 0; j < 4; j++) {
                    od[j] = __shfl_xor_sync(0xffffffffu, md[j], off);
                    oi[j] = __shfl_xor_sync(0xffffffffu, mi[j], off);
                }
#pragma unroll
                for (int j = 0; j < 4; j++) t4_insert(md, mi, od[j], oi[j]);
            }
            if ((lane & 3) == 0) {
                int mt = q >> 1, half = q & 1;
                int tok = (wm * 2 + mt) * 16 + g + half * 8;
                htd[wn * TM + tok] = make_float4(md[0], md[1], md[2], md[3]);
                hti[wn * TM + tok] = make_int4(mi[0], mi[1], mi[2], mi[3]);
            }
        }
        __syncthreads();

        // ---- cross-half merge + decision (one thread per token) ----------
        if (tid < TM) {
            float4 d0 = htd[tid];       int4 i0 = hti[tid];
            float4 d1 = htd[TM + tid];  int4 i1 = hti[TM + tid];
            float md[4] = { d0.x, d0.y, d0.z, d0.w };
            int   mi[4] = { i0.x, i0.y, i0.z, i0.w };
            t4_insert(md, mi, d1.x, i1.x);
            t4_insert(md, mi, d1.y, i1.y);
            t4_insert(md, mi, d1.z, i1.z);
            t4_insert(md, mi, d1.w, i1.w);
            if (md[1] >= md[0] + MARGIN) {
                bestI[tid] = mi[0];
            } else {
                int p = atomicAdd(candCnt, 1);
                candTok[p] = tid;
                candIdx[tid] = make_int4(mi[0], mi[1], mi[2], mi[3]);
            }
        }
        __syncthreads();

        // ---- rescue: exact fp32 dots for flagged tokens (warp per entry) -
        {
            int cnt = *candCnt;
            for (int e = wid; e < cnt; e += 8) {
                int tok = candTok[e];
                int4 cs = candIdx[tok];
                float r2t = r2Sh[tok];
                const float* rrow = Rsh + tok * RS + lane * 8;
                float bd = INF; int bi = 0x7fffffff;
#pragma unroll
                for (int j = 0; j < 4; j++) {
                    int idx = (&cs.x)[j];
                    const float* crow = CB + ((size_t)lvl * KCODES + idx) * DDIM + lane * 8;
                    float p = 0.f;
#pragma unroll
                    for (int u = 0; u < 8; u++) p = fmaf(rrow[u], crow[u], p);
#pragma unroll
                    for (int o = 16; o; o >>= 1) p += __shfl_xor_sync(0xffffffffu, p, o);
                    float dd = fmaf(-2.f, p, r2t + e2Sh[idx]);
                    if (dd < bd || (dd == bd && idx < bi)) { bd = dd; bi = idx; }
                }
                if (lane == 0) bestI[tok] = bi;
            }
        }
        __syncthreads();

        // ---- residual update + new r2 + commit ---------------------------
        {
            int t = tid >> 1, h = tid & 1;
            int b = bestI[t];
            const float* qv = CB + ((size_t)lvl * KCODES + b) * DDIM + h * 128;
            float* rr = Rsh + t * RS + h * 128;
            double ss = 0.0;
            for (int k = 0; k < 128; k += 4) {
                float4 q4 = *(const float4*)(qv + k);
                float n0 = rr[k]     - q4.x;
                float n1 = rr[k + 1] - q4.y;
                float n2 = rr[k + 2] - q4.z;
                float n3 = rr[k + 3] - q4.w;
                rr[k] = n0; rr[k + 1] = n1; rr[k + 2] = n2; rr[k + 3] = n3;
                ss += (double)n0 * n0 + (double)n1 * n1
                    + (double)n2 * n2 + (double)n3 * n3;
            }
            redD[tid] = ss;
            commitAcc += ss;
            __syncthreads();
            if (!h) r2Sh[t] = (float)(redD[tid] + redD[tid + 1]);
        }
        __syncthreads();
    } // levels

    // ---- y = x - r_final ---------------------------------------------------
    for (int idx = tid; idx < TM * (DDIM / 4); idx += THREADS) {
        int t = idx >> 6, dq = (idx & 63) << 2;
        float4 xv = *(const float4*)(Xblk + (long long)t * DDIM + dq);
        const float* rr = Rsh + t * RS + dq;
        float4 y;
        y.x = xv.x - rr[0]; y.y = xv.y - rr[1];
        y.z = xv.z - rr[2]; y.w = xv.w - rr[3];
        *(float4*)(Y + (tokenBase + t) * DDIM + dq) = y;
    }

    // ---- deterministic per-block commit partial ----------------------------
    redD[tid] = commitAcc;
    for (int s = THREADS / 2; s > 0; s >>= 1) {
        __syncthreads();
        if (tid < s) redD[tid] += redD[tid + s];
    }
    if (tid == 0) g_commitPartial[blockIdx.x] = redD[0];
}

// ---------------------------------------------------------------------------
// Final reduction -> commit scalar appended after y
// ---------------------------------------------------------------------------
__global__ void finalize_kernel(float* __restrict__ Y, int out_size) {
    __shared__ double sd[NBLOCKS];
    int tid = threadIdx.x;
    sd[tid] = g_commitPartial[tid];
    for (int s = NBLOCKS / 2; s > 0; s >>= 1) {
        __syncthreads();
        if (tid < s) sd[tid] += sd[tid + s];
    }
    if (tid == 0) {
        double mean = sd[0] / (double)((long long)NTOK * DDIM);
        float commit = (float)(0.25 * mean);
        long long numel = (long long)NTOK * DDIM;
        for (long long j = numel; j < (long long)out_size; j++) Y[j] = commit;
    }
}

extern "C" void kernel_launch(void* const* d_in, const int* in_sizes, int n_in,
                              void* d_out, int out_size) {
    const float* X  = (const float*)d_in[0];
    const float* CB = (const float*)d_in[1];
    float* Y = (float*)d_out;

    cudaFuncSetAttribute(rvq_mma, cudaFuncAttributeMaxDynamicSharedMemorySize,
                         SMEM_TOTAL);

    e2_kernel<<<(MLVL * KCODES * 32 + 255) / 256, 256>>>(CB);
    prep_cb<<<(MLVL * 64 * 512 + 255) / 256, 256>>>(CB);
    rvq_mma<<<NBLOCKS, THREADS, SMEM_TOTAL>>>(X, CB, Y);
    finalize_kernel<<<1, NBLOCKS>>>(Y, out_size);
}

// round 5
// speedup vs baseline: 4.5840x; 1.1105x over previous
#include <cuda_runtime.h>
#include <cuda_bf16.h>
#include <cstdint>

// Problem constants
#define NTOK    65536
#define DDIM    256
#define KCODES  1024
#define MLVL    4
#define TM      128            // tokens per block
#define THREADS 512
#define RS      260            // fp32 residual row stride (floats)
#define NBLOCKS (NTOK / TM)    // 512
#define MARGIN  4e-4f
#define NSTAGE  3

// SMEM byte offsets (dynamic smem, total 228880 <= 232448)
#define OFF_RSH    0                   // 133120: [128][260] fp32 residual
#define OFF_AFRAG  133120              // 65536:  A fragments [mt8][ks16][lane32]
#define OFF_BBUF   198656              // 24576:  3 x 8KB B slices (ring)
// Overlays inside the BBUF region (dead while in use; barrier-separated):
#define OFF_HTD    198656              // float4 halfTopDist[2][128] (4KB)
#define OFF_HTI    202752              // int4   halfTopIdx [2][128] (4KB)
#define OFF_CIDX   206848              // int4   candIdx[128]        (2KB)
#define OFF_REDD   210944              // double redD[512]           (4KB)
#define OFF_E2     223232              // 4096
#define OFF_R2     227328              // 512
#define OFF_BEST   227840              // 512
#define OFF_CTOK   228352              // 512
#define OFF_CCNT   228864              // 16
#define SMEM_TOTAL 228880

__device__ float  g_e2[MLVL * KCODES];
__device__ double g_commitPartial[NBLOCKS];
// B fragments: [lvl][slice(64)][512 x uint4]  (slice = nc*8 + kb, 8KB each)
__device__ uint4  g_cbfrag[MLVL * 64 * 512];

static __device__ __forceinline__ uint32_t pkbf(float a, float b) {
    __nv_bfloat162 h = __floats2bfloat162_rn(a, b);
    return *reinterpret_cast<uint32_t*>(&h);
}
static __device__ __forceinline__ void mma16816(float* c, const uint4& A,
                                                uint32_t b0, uint32_t b1) {
    asm volatile(
        "mma.sync.aligned.m16n8k16.row.col.f32.bf16.bf16.f32 "
        "{%0,%1,%2,%3}, {%4,%5,%6,%7}, {%8,%9}, {%0,%1,%2,%3};"
        : "+f"(c[0]), "+f"(c[1]), "+f"(c[2]), "+f"(c[3])
        : "r"(A.x), "r"(A.y), "r"(A.z), "r"(A.w), "r"(b0), "r"(b1));
}
static __device__ __forceinline__ void cpasync16(void* dst, const void* src) {
    uint32_t d = (uint32_t)__cvta_generic_to_shared(dst);
    asm volatile("cp.async.cg.shared.global [%0], [%1], 16;" :: "r"(d), "l"(src));
}
#define CP_COMMIT() asm volatile("cp.async.commit_group;")
#define CP_WAIT(n)  asm volatile("cp.async.wait_group %0;" :: "n"(n))

// ---------------------------------------------------------------------------
__global__ void e2_kernel(const float* __restrict__ cb) {
    int warp = (blockIdx.x * blockDim.x + threadIdx.x) >> 5;
    int lane = threadIdx.x & 31;
    if (warp >= MLVL * KCODES) return;
    const float* row = cb + (size_t)warp * DDIM;
    double s = 0.0;
#pragma unroll
    for (int m = 0; m < DDIM / 32; m++) {
        float v = row[lane + 32 * m];
        s += (double)v * (double)v;
    }
#pragma unroll
    for (int off = 16; off; off >>= 1) s += __shfl_xor_sync(0xffffffffu, s, off);
    if (lane == 0) g_e2[warp] = (float)s;
}

// ---------------------------------------------------------------------------
// Pre-pack codebooks as bf16 m16n8k16 B-fragments.
// n = nc*128 + half*64 + nt*8 + (lane>>2), k0 = kb*32 + (lane&3)*2
// ---------------------------------------------------------------------------
__global__ void prep_cb(const float* __restrict__ cb) {
    int id = blockIdx.x * blockDim.x + threadIdx.x;
    if (id >= MLVL * 64 * 512) return;
    int s    = id >> 9;
    int u    = id & 511;
    int half = u >> 8;
    int nt   = (u >> 5) & 7;
    int lane = u & 31;
    int lvl  = s >> 6;
    int nc   = (s >> 3) & 7;
    int kb   = s & 7;
    int n  = nc * 128 + half * 64 + nt * 8 + (lane >> 2);
    int k0 = kb * 32 + (lane & 3) * 2;
    const float* row = cb + ((size_t)lvl * KCODES + n) * DDIM;
    uint4 v;
    v.x = pkbf(row[k0],      row[k0 + 1]);
    v.y = pkbf(row[k0 + 8],  row[k0 + 9]);
    v.z = pkbf(row[k0 + 16], row[k0 + 17]);
    v.w = pkbf(row[k0 + 24], row[k0 + 25]);
    g_cbfrag[id] = v;
}

// ---------------------------------------------------------------------------
struct Top3 { float d0, d1, d2; int i0, i1, i2; };
static __device__ __forceinline__ void t3_insert(Top3& T, float d, int idx) {
    if (d < T.d2) {
        if (d < T.d1) {
            T.d2 = T.d1; T.i2 = T.i1;
            if (d < T.d0) { T.d1 = T.d0; T.i1 = T.i0; T.d0 = d; T.i0 = idx; }
            else          { T.d1 = d;    T.i1 = idx; }
        } else { T.d2 = d; T.i2 = idx; }
    }
}
static __device__ __forceinline__ void t4_insert(float* d, int* i, float nd, int ni) {
    bool l3 = (nd < d[3]) || (nd == d[3] && ni < i[3]);
    if (!l3) return;
    bool l2 = (nd < d[2]) || (nd == d[2] && ni < i[2]);
    bool l1 = (nd < d[1]) || (nd == d[1] && ni < i[1]);
    bool l0 = (nd < d[0]) || (nd == d[0] && ni < i[0]);
    if (l0)      { d[3]=d[2]; i[3]=i[2]; d[2]=d[1]; i[2]=i[1]; d[1]=d[0]; i[1]=i[0]; d[0]=nd; i[0]=ni; }
    else if (l1) { d[3]=d[2]; i[3]=i[2]; d[2]=d[1]; i[2]=i[1]; d[1]=nd; i[1]=ni; }
    else if (l2) { d[3]=d[2]; i[3]=i[2]; d[2]=nd; i[2]=ni; }
    else         { d[3]=nd; i[3]=ni; }
}

// ---------------------------------------------------------------------------
// Main fused residual-VQ kernel. 512 threads, 16 warps, 3-stage cp.async ring.
// Warp tile: 16 tokens (wm) x 64 codes (wn half of each 128-chunk).
// ---------------------------------------------------------------------------
__global__ __launch_bounds__(THREADS, 1)
void rvq_mma(const float* __restrict__ X, const float* __restrict__ CB,
             float* __restrict__ Y) {
    extern __shared__ char smem[];
    float*  Rsh     = (float*)(smem + OFF_RSH);
    uint4*  Af      = (uint4*)(smem + OFF_AFRAG);
    uint4*  Bb      = (uint4*)(smem + OFF_BBUF);
    float4* htd     = (float4*)(smem + OFF_HTD);
    int4*   hti     = (int4*)(smem + OFF_HTI);
    int4*   candIdx = (int4*)(smem + OFF_CIDX);
    double* redD    = (double*)(smem + OFF_REDD);
    float*  e2Sh    = (float*)(smem + OFF_E2);
    float*  r2Sh    = (float*)(smem + OFF_R2);
    int*    bestI   = (int*)(smem + OFF_BEST);
    int*    candTok = (int*)(smem + OFF_CTOK);
    int*    candCnt = (int*)(smem + OFF_CCNT);

    const int tid  = threadIdx.x;
    const int wid  = tid >> 5;
    const int lane = tid & 31;
    const int wm   = wid & 7;    // M tile: rows [wm*16, wm*16+16)
    const int wn   = wid >> 3;   // N half within each 128-code chunk
    const int g    = lane >> 2;  // groupID
    const int tg2  = (lane & 3) * 2;
    const long long tokenBase = (long long)blockIdx.x * TM;
    const float* Xblk = X + tokenBase * DDIM;
    const float INF = __int_as_float(0x7f800000);

    // ---- load X tile -----------------------------------------------------
    for (int idx = tid; idx < TM * (DDIM / 4); idx += THREADS) {
        int t = idx >> 6, dq = (idx & 63) << 2;
        *(float4*)(Rsh + t * RS + dq) = *(const float4*)(Xblk + (long long)t * DDIM + dq);
    }
    __syncthreads();

    // ---- initial r2 (fp64 -> fp32), redD overlays Bb (no prefetch yet) ---
    {
        int t = tid >> 2, h = tid & 3;
        const float* rr = Rsh + t * RS + h * 64;
        double s = 0.0;
        for (int k = 0; k < 64; k++) { float f = rr[k]; s += (double)f * f; }
        redD[tid] = s;
        __syncthreads();
        if (!h) r2Sh[t] = (float)(redD[tid] + redD[tid + 1] + redD[tid + 2] + redD[tid + 3]);
    }
    __syncthreads();

    double commitAcc = 0.0;

    for (int lvl = 0; lvl < MLVL; lvl++) {
        // ---- level setup: e2, candCnt, A fragments (bf16) ----------------
        if (tid == 0) *candCnt = 0;
        for (int i = tid; i < KCODES; i += THREADS) e2Sh[i] = g_e2[lvl * KCODES + i];
        for (int idx = tid; idx < 8 * 16 * 32; idx += THREADS) {
            int mt = idx >> 9, ks = (idx >> 5) & 15, ln = idx & 31;
            int m0 = mt * 16 + (ln >> 2);
            int k0 = ks * 16 + (ln & 3) * 2;
            const float* ra = Rsh + m0 * RS;
            const float* rb = Rsh + (m0 + 8) * RS;
            uint4 v;
            v.x = pkbf(ra[k0],     ra[k0 + 1]);
            v.y = pkbf(rb[k0],     rb[k0 + 1]);
            v.z = pkbf(ra[k0 + 8], ra[k0 + 9]);
            v.w = pkbf(rb[k0 + 8], rb[k0 + 9]);
            Af[idx] = v;
        }
        __syncthreads();   // Af ready; Bb overlays (redD etc.) dead below

        const float r2a = r2Sh[wm * 16 + g];
        const float r2b = r2Sh[wm * 16 + g + 8];

        Top3 T[2];
#pragma unroll
        for (int q = 0; q < 2; q++) { T[q].d0 = T[q].d1 = T[q].d2 = INF; T[q].i0 = T[q].i1 = T[q].i2 = 0x7fffffff; }

        const uint4* gb = g_cbfrag + (size_t)lvl * 64 * 512;

        // ---- prologue: prefetch stages 0,1 (one 16B per thread each) -----
        cpasync16(Bb + 0 * 512 + tid, gb + 0 * 512 + tid);
        CP_COMMIT();
        cpasync16(Bb + 1 * 512 + tid, gb + 1 * 512 + tid);
        CP_COMMIT();

        float acc[8][4];
        int cur = 0;

        for (int sl = 0; sl < 64; sl++) {
            const int kb = sl & 7;
            CP_WAIT(1);        // stage sl landed
            __syncthreads();   // visible to all; all done with buf (sl-1)%3
            if (sl + 2 < 64) {
                int nb = cur == 0 ? 2 : cur - 1;   // (sl+2)%3
                cpasync16(Bb + nb * 512 + tid, gb + (size_t)(sl + 2) * 512 + tid);
            }
            CP_COMMIT();       // unconditional: keeps group indexing uniform

            if (kb == 0) {
#pragma unroll
                for (int nt = 0; nt < 8; nt++)
#pragma unroll
                    for (int c = 0; c < 4; c++) acc[nt][c] = 0.f;
            }

            uint4 A0 = Af[(wm * 16 + kb * 2 + 0) * 32 + lane];
            uint4 A1 = Af[(wm * 16 + kb * 2 + 1) * 32 + lane];
            const uint4* Bp = Bb + cur * 512 + wn * 256 + lane;
#pragma unroll
            for (int nt = 0; nt < 8; nt++) {
                uint4 Bv = Bp[nt * 32];
                mma16816(acc[nt], A0, Bv.x, Bv.y);
                mma16816(acc[nt], A1, Bv.z, Bv.w);
            }

            // ---- per-chunk epilogue: dist + top-3 streaming --------------
            if (kb == 7) {
                const int nc = sl >> 3;
#pragma unroll
                for (int nt = 0; nt < 8; nt++) {
                    int nbase = nc * 128 + wn * 64 + nt * 8 + tg2;
                    float2 e2p = *(const float2*)&e2Sh[nbase];
                    t3_insert(T[0], fmaf(-2.f, acc[nt][0], r2a + e2p.x), nbase);
                    t3_insert(T[0], fmaf(-2.f, acc[nt][1], r2a + e2p.y), nbase + 1);
                    t3_insert(T[1], fmaf(-2.f, acc[nt][2], r2b + e2p.x), nbase);
                    t3_insert(T[1], fmaf(-2.f, acc[nt][3], r2b + e2p.y), nbase + 1);
                }
            }
            cur = cur == 2 ? 0 : cur + 1;
        } // slices

        __syncthreads();   // all compute done before htd/hti overlay Bb

        // ---- quad merge, publish per-(wn,token) top-4 to SMEM ------------
#pragma unroll
        for (int q = 0; q < 2; q++) {
            float md[4] = { T[q].d0, T[q].d1, T[q].d2, INF };
            int   mi[4] = { T[q].i0, T[q].i1, T[q].i2, 0x7fffffff };
#pragma unroll
            for (int off = 1; off <= 2; off <<= 1) {
                float od[4]; int oi[4];
#pragma unroll
                for (int j = 0; j < 4; j++) {
                    od[j] = __shfl_xor_sync(0xffffffffu, md[j], off);
                    oi[j] = __shfl_xor_sync(0xffffffffu, mi[j], off);
                }
#pragma unroll
                for (int j = 0; j < 4; j++) t4_insert(md, mi, od[j], oi[j]);
            }
            if ((lane & 3) == 0) {
                int tok = wm * 16 + g + q * 8;
                htd[wn * TM + tok] = make_float4(md[0], md[1], md[2], md[3]);
                hti[wn * TM + tok] = make_int4(mi[0], mi[1], mi[2], mi[3]);
            }
        }
        __syncthreads();

        // ---- cross-half merge + decision (one thread per token) ----------
        if (tid < TM) {
            float4 d0 = htd[tid];       int4 i0 = hti[tid];
            float4 d1 = htd[TM + tid];  int4 i1 = hti[TM + tid];
            float md[4] = { d0.x, d0.y, d0.z, d0.w };
            int   mi[4] = { i0.x, i0.y, i0.z, i0.w };
            t4_insert(md, mi, d1.x, i1.x);
            t4_insert(md, mi, d1.y, i1.y);
            t4_insert(md, mi, d1.z, i1.z);
            t4_insert(md, mi, d1.w, i1.w);
            if (md[1] >= md[0] + MARGIN) {
                bestI[tid] = mi[0];
            } else {
                int p = atomicAdd(candCnt, 1);
                candTok[p] = tid;
                candIdx[tid] = make_int4(mi[0], mi[1], mi[2], mi[3]);
            }
        }
        __syncthreads();

        // ---- rescue: exact fp32 dots for flagged tokens (warp per entry) -
        {
            int cnt = *candCnt;
            for (int e = wid; e < cnt; e += 16) {
                int tok = candTok[e];
                int4 cs = candIdx[tok];
                float r2t = r2Sh[tok];
                const float* rrow = Rsh + tok * RS + lane * 8;
                float bd = INF; int bi = 0x7fffffff;
#pragma unroll
                for (int j = 0; j < 4; j++) {
                    int idx = (&cs.x)[j];
                    const float* crow = CB + ((size_t)lvl * KCODES + idx) * DDIM + lane * 8;
                    float p = 0.f;
#pragma unroll
                    for (int u = 0; u < 8; u++) p = fmaf(rrow[u], crow[u], p);
#pragma unroll
                    for (int o = 16; o; o >>= 1) p += __shfl_xor_sync(0xffffffffu, p, o);
                    float dd = fmaf(-2.f, p, r2t + e2Sh[idx]);
                    if (dd < bd || (dd == bd && idx < bi)) { bd = dd; bi = idx; }
                }
                if (lane == 0) bestI[tok] = bi;
            }
        }
        __syncthreads();

        // ---- residual update + new r2 + commit (4 threads / token) -------
        {
            int t = tid >> 2, h = tid & 3;
            int b = bestI[t];
            const float* qv = CB + ((size_t)lvl * KCODES + b) * DDIM + h * 64;
            float* rr = Rsh + t * RS + h * 64;
            double ss = 0.0;
            for (int k = 0; k < 64; k += 4) {
                float4 q4 = *(const float4*)(qv + k);
                float n0 = rr[k]     - q4.x;
                float n1 = rr[k + 1] - q4.y;
                float n2 = rr[k + 2] - q4.z;
                float n3 = rr[k + 3] - q4.w;
                rr[k] = n0; rr[k + 1] = n1; rr[k + 2] = n2; rr[k + 3] = n3;
                ss += (double)n0 * n0 + (double)n1 * n1
                    + (double)n2 * n2 + (double)n3 * n3;
            }
            redD[tid] = ss;
            commitAcc += ss;
            __syncthreads();
            if (!h) r2Sh[t] = (float)(redD[tid] + redD[tid + 1] + redD[tid + 2] + redD[tid + 3]);
        }
        __syncthreads();
    } // levels

    // ---- y = x - r_final ---------------------------------------------------
    for (int idx = tid; idx < TM * (DDIM / 4); idx += THREADS) {
        int t = idx >> 6, dq = (idx & 63) << 2;
        float4 xv = *(const float4*)(Xblk + (long long)t * DDIM + dq);
        const float* rr = Rsh + t * RS + dq;
        float4 y;
        y.x = xv.x - rr[0]; y.y = xv.y - rr[1];
        y.z = xv.z - rr[2]; y.w = xv.w - rr[3];
        *(float4*)(Y + (tokenBase + t) * DDIM + dq) = y;
    }

    // ---- deterministic per-block commit partial ----------------------------
    redD[tid] = commitAcc;
    for (int s = THREADS / 2; s > 0; s >>= 1) {
        __syncthreads();
        if (tid < s) redD[tid] += redD[tid + s];
    }
    if (tid == 0) g_commitPartial[blockIdx.x] = redD[0];
}

// ---------------------------------------------------------------------------
__global__ void finalize_kernel(float* __restrict__ Y, int out_size) {
    __shared__ double sd[NBLOCKS];
    int tid = threadIdx.x;
    sd[tid] = g_commitPartial[tid];
    for (int s = NBLOCKS / 2; s > 0; s >>= 1) {
        __syncthreads();
        if (tid < s) sd[tid] += sd[tid + s];
    }
    if (tid == 0) {
        double mean = sd[0] / (double)((long long)NTOK * DDIM);
        float commit = (float)(0.25 * mean);
        long long numel = (long long)NTOK * DDIM;
        for (long long j = numel; j < (long long)out_size; j++) Y[j] = commit;
    }
}

extern "C" void kernel_launch(void* const* d_in, const int* in_sizes, int n_in,
                              void* d_out, int out_size) {
    const float* X  = (const float*)d_in[0];
    const float* CB = (const float*)d_in[1];
    float* Y = (float*)d_out;

    cudaFuncSetAttribute(rvq_mma, cudaFuncAttributeMaxDynamicSharedMemorySize,
                         SMEM_TOTAL);

    e2_kernel<<<(MLVL * KCODES * 32 + 255) / 256, 256>>>(CB);
    prep_cb<<<(MLVL * 64 * 512 + 255) / 256, 256>>>(CB);
    rvq_mma<<<NBLOCKS, THREADS, SMEM_TOTAL>>>(X, CB, Y);
    finalize_kernel<<<1, NBLOCKS>>>(Y, out_size);
}